// round 1
// baseline (speedup 1.0000x reference)
#include <cuda_runtime.h>

// IndRNN recurrence: h_t = relu(h_{t-1} * w[h] + x[t,b,h]), out[t,b,h] = h_t
// x: [T, B, H] fp32, w: [H], h0: [B, H] (zeros), out: [T, B, H]
// T=1024, B=64, H=1024. One thread per (b,h) channel; sequential scan over T.
// x-loads are independent of the recurrence chain -> prefetch UNROLL ahead
// to build memory-level parallelism (4 MB outstanding chip-wide).

#define T_STEPS 1024
#define B_DIM 64
#define H_DIM 1024
#define BH (B_DIM * H_DIM)
#define UNROLL 16

__global__ __launch_bounds__(128, 16)
void indrnn_kernel(const float* __restrict__ x,
                   const float* __restrict__ w,
                   const float* __restrict__ h0,
                   float* __restrict__ out) {
    const int idx = blockIdx.x * blockDim.x + threadIdx.x;  // 0 .. BH-1
    const int hcol = idx & (H_DIM - 1);

    const float wv = __ldg(&w[hcol]);
    float h = h0[idx];

    const float* xp = x + idx;
    float* op = out + idx;

    float xv[UNROLL];

    #pragma unroll 1
    for (int t = 0; t < T_STEPS; t += UNROLL) {
        // Batch-issue the independent x loads first (front-batched LDGs -> MLP)
        #pragma unroll
        for (int i = 0; i < UNROLL; i++) {
            xv[i] = __ldg(xp + (long long)(t + i) * BH);
        }
        // Dependent recurrence chain + stores
        #pragma unroll
        for (int i = 0; i < UNROLL; i++) {
            h = fmaxf(fmaf(h, wv, xv[i]), 0.0f);
            op[(long long)(t + i) * BH] = h;
        }
    }
}

extern "C" void kernel_launch(void* const* d_in, const int* in_sizes, int n_in,
                              void* d_out, int out_size) {
    const float* x  = (const float*)d_in[0];   // [T, B, H]
    const float* w  = (const float*)d_in[1];   // [H]
    const float* h0 = (const float*)d_in[2];   // [B, H]
    float* out = (float*)d_out;                // [T, B, H]

    const int threads = 128;
    const int blocks = BH / threads;           // 512 blocks
    indrnn_kernel<<<blocks, threads>>>(x, w, h0, out);
}